// round 4
// baseline (speedup 1.0000x reference)
#include <cuda_runtime.h>
#include <math_constants.h>

// Problem constants (KnnEdges: B=4, M=8192, D=2, k=16)
#define B_   4
#define M_   8192
#define N_   (B_ * M_)          // 32768
#define K_   16
#define NE_  (N_ * K_)          // 524288

// Spatial grid: cell = 16.0 (power of two -> exact binning/bounds), 63x63 cells
#define G_    63
#define GG_   (G_ * G_)         // 3969
#define INVH_ 0.0625f

// Output layout (float32 concat of reference tuple)
#define OFF_X     0
#define OFF_POSP  2097152
#define OFF_EIDX  2162688
#define OFF_EW    3211264
#define OFF_BATCH 3735552
#define OFF_PERM  3768320
#define OFF_SCORE 3801088

__device__ int      g_cnt[B_][GG_ + 1];   // counts -> exclusive starts; [GG_] = M
__device__ int      g_rank[N_];           // per-point rank within its cell
__device__ float4   g_pts[N_];            // grid-sorted (x, y, idx_bits, 0)
__device__ unsigned g_maxbits;

__device__ __forceinline__ int cell_of(float v) {
    int c = (int)(v * INVH_);
    return c > G_ - 1 ? G_ - 1 : (c < 0 ? 0 : c);
}

// ---------------------------------------------------------------------------
__global__ void zero_kernel() {
    int t = blockIdx.x * blockDim.x + threadIdx.x;
    if (t == 0) g_maxbits = 0u;
    if (t < B_ * (GG_ + 1)) ((int*)g_cnt)[t] = 0;
}

// ---------------------------------------------------------------------------
// Copies/casts/gather + grid cell counting (saves rank for atomic-free
// scatter). batch/perm are int32 on device (JAX x64 disabled).
// ---------------------------------------------------------------------------
__global__ void prep_kernel(const float* __restrict__ x,
                            const float* __restrict__ pos,
                            const int* __restrict__ perm,
                            const float* __restrict__ score,
                            float* __restrict__ out) {
    int t = blockIdx.x * blockDim.x + threadIdx.x;

    const int C_X4 = (N_ * 64) / 4;        // 524288
    if (t < C_X4) {
        ((float4*)(out + OFF_X))[t] = ((const float4*)x)[t];
        return;
    }
    t -= C_X4;
    if (t < N_) {                          // pos gather + cell count
        int p = perm[t];
        float2 v = ((const float2*)pos)[p];
        ((float2*)(out + OFF_POSP))[t] = v;
        int b = t >> 13;
        int c = cell_of(v.y) * G_ + cell_of(v.x);
        g_rank[t] = atomicAdd(&g_cnt[b][c], 1);
        return;
    }
    t -= N_;
    if (t < NE_ / 4) {                     // tgt row, float4
        int base = 4 * t;
        ((float4*)(out + OFF_EIDX + NE_))[t] =
            make_float4((float)(base >> 4), (float)((base + 1) >> 4),
                        (float)((base + 2) >> 4), (float)((base + 3) >> 4));
        return;
    }
    t -= NE_ / 4;
    if (t < N_ / 4) {                      // batch cast, float4
        int base = 4 * t;
        ((float4*)(out + OFF_BATCH))[t] =
            make_float4((float)(base >> 13), (float)((base + 1) >> 13),
                        (float)((base + 2) >> 13), (float)((base + 3) >> 13));
        return;
    }
    t -= N_ / 4;
    if (t < N_ / 4) {                      // perm cast, float4
        int4 p = ((const int4*)perm)[t];
        ((float4*)(out + OFF_PERM))[t] =
            make_float4((float)p.x, (float)p.y, (float)p.z, (float)p.w);
        return;
    }
    t -= N_ / 4;
    if (t < N_ / 4) {                      // score copy, float4
        ((float4*)(out + OFF_SCORE))[t] = ((const float4*)score)[t];
        return;
    }
}

// ---------------------------------------------------------------------------
// Per-batch exclusive prefix sum over GG_ cell counts (one CTA per batch).
// ---------------------------------------------------------------------------
__global__ void __launch_bounds__(1024) scan_kernel() {
    __shared__ int sh[1024];
    const int b = blockIdx.x;
    const int t = threadIdx.x;
    const int base = t * 4;

    int v[4], tot = 0;
#pragma unroll
    for (int i = 0; i < 4; i++) {
        v[i] = (base + i < GG_) ? g_cnt[b][base + i] : 0;
        tot += v[i];
    }
    sh[t] = tot;
    __syncthreads();
    for (int off = 1; off < 1024; off <<= 1) {
        int u = (t >= off) ? sh[t - off] : 0;
        __syncthreads();
        sh[t] += u;
        __syncthreads();
    }
    int run = sh[t] - tot;   // exclusive
#pragma unroll
    for (int i = 0; i < 4; i++) {
        if (base + i < GG_) g_cnt[b][base + i] = run;
        run += v[i];
    }
    if (t == 1023) g_cnt[b][GG_] = run;   // = M_
}

// ---------------------------------------------------------------------------
// Scatter points into grid-sorted order using saved ranks (no atomics).
// ---------------------------------------------------------------------------
__global__ void __launch_bounds__(128) scatter_kernel(const float* __restrict__ out) {
    int t = blockIdx.x * blockDim.x + threadIdx.x;
    if (t >= N_) return;
    int b = t >> 13, i = t & (M_ - 1);
    float2 v = ((const float2*)(out + OFF_POSP))[t];
    int c = cell_of(v.y) * G_ + cell_of(v.x);
    int dst = g_cnt[b][c] + g_rank[t];
    g_pts[b * M_ + dst] = make_float4(v.x, v.y, __int_as_float(i), 0.0f);
}

// ---------------------------------------------------------------------------
// Exact KNN via expanding-ring grid search with contiguous row segments.
// Top-16 kept as packed u64 keys (d2_bits<<32 | idx): integer order ==
// lexicographic (d2 asc, idx asc) == jax.lax.top_k(-d2) output order.
// Keys live in a local-memory array with a dynamic-depth shift loop;
// key[15] mirrored in a register for the hot-path compare.
// d2 uses explicit rn ops (no FMA) to bit-match XLA's sub/mul/mul/add.
// Stop bound: unvisited ring >= r implies d >= (r-1)*16 (exact in fp).
// ---------------------------------------------------------------------------
__global__ void __launch_bounds__(128) knn_kernel(float* __restrict__ out) {
    int t = blockIdx.x * 128 + threadIdx.x;
    int b = t >> 13, s = t & (M_ - 1);

    const float4* __restrict__ pts = g_pts + b * M_;
    const int*    __restrict__ cs  = g_cnt[b];

    float4 q = pts[s];
    int qi = __float_as_int(q.z);
    int cx = cell_of(q.x), cy = cell_of(q.y);

    unsigned long long key[K_];
#pragma unroll
    for (int u = 0; u < K_; u++) key[u] = 0xFFFFFFFFFFFFFFFFull;
    unsigned long long k15 = 0xFFFFFFFFFFFFFFFFull;   // mirror of key[15]

#define PROCESS_SEG(XA, XB, YY)                                                \
    {                                                                          \
        int c0_ = (YY) * G_ + (XA);                                            \
        int js_ = cs[c0_], je_ = cs[c0_ + ((XB) - (XA)) + 1];                  \
        for (int j_ = js_; j_ < je_; j_++) {                                   \
            float4 v_ = pts[j_];                                               \
            float dx_ = __fsub_rn(q.x, v_.x);                                  \
            float dy_ = __fsub_rn(q.y, v_.y);                                  \
            float d2_ = __fadd_rn(__fmul_rn(dx_, dx_), __fmul_rn(dy_, dy_));   \
            unsigned long long nk_ =                                           \
                ((unsigned long long)__float_as_uint(d2_) << 32) |             \
                (unsigned)__float_as_int(v_.z);                                \
            if (nk_ < k15) {                                                   \
                unsigned long long c14_ = key[K_ - 2];                         \
                if (c14_ <= nk_) {                                             \
                    key[K_ - 1] = nk_; k15 = nk_;                              \
                } else {                                                       \
                    key[K_ - 1] = c14_; k15 = c14_;                            \
                    int u_ = K_ - 2;                                           \
                    while (u_ > 0) {                                           \
                        unsigned long long p_ = key[u_ - 1];                   \
                        if (p_ <= nk_) break;                                  \
                        key[u_] = p_;                                          \
                        u_--;                                                  \
                    }                                                          \
                    key[u_] = nk_;                                             \
                }                                                              \
            }                                                                  \
        }                                                                      \
    }

    for (int r = 0; r < G_; r++) {
        if (r >= 2) {
            float bound = (float)(r - 1) * 16.0f;                    // exact
            float bd15 = __uint_as_float((unsigned)(k15 >> 32));
            if (bd15 < bound * bound) break;                         // strict
        }
        int x0 = cx - r, x1 = cx + r, y0 = cy - r, y1 = cy + r;
        int xa = x0 < 0 ? 0 : x0, xb = x1 > G_ - 1 ? G_ - 1 : x1;
        if (y0 >= 0)             PROCESS_SEG(xa, xb, y0);
        if (r > 0 && y1 <= G_-1) PROCESS_SEG(xa, xb, y1);
        int ya = (y0 + 1) < 0 ? 0 : (y0 + 1);
        int yb = (y1 - 1) > G_ - 1 ? G_ - 1 : (y1 - 1);
        if (r > 0) {
            for (int yy = ya; yy <= yb; yy++) {
                if (x0 >= 0)      PROCESS_SEG(x0, x0, yy);
                if (x1 <= G_ - 1) PROCESS_SEG(x1, x1, yy);
            }
        }
    }
#undef PROCESS_SEG

    const int tgt = b * M_ + qi;
    float lmax = 0.0f;
#pragma unroll
    for (int u = 0; u < K_; u++) {
        unsigned long long kk = key[u];
        out[OFF_EIDX + tgt * K_ + u] = (float)(b * M_ + (int)(kk & 0xFFFFFFFFu));
        float dist = __fsqrt_rn(__uint_as_float((unsigned)(kk >> 32)));
        out[OFF_EW + tgt * K_ + u] = dist;
        lmax = fmaxf(lmax, dist);
    }
#pragma unroll
    for (int o = 16; o; o >>= 1)
        lmax = fmaxf(lmax, __shfl_xor_sync(0xffffffffu, lmax, o));
    if ((threadIdx.x & 31) == 0)
        atomicMax(&g_maxbits, __float_as_uint(lmax));
}

// ---------------------------------------------------------------------------
__global__ void norm_kernel(float* __restrict__ out) {
    int t = blockIdx.x * blockDim.x + threadIdx.x;
    float m = __uint_as_float(g_maxbits);
    float4 v = ((const float4*)(out + OFF_EW))[t];
    ((float4*)(out + OFF_EW))[t] =
        make_float4(v.x / m, v.y / m, v.z / m, v.w / m);
}

extern "C" void kernel_launch(void* const* d_in, const int* in_sizes, int n_in,
                              void* d_out, int out_size) {
    const float* x     = (const float*)d_in[0];
    const float* pos   = (const float*)d_in[1];
    const int*   perm  = (const int*)d_in[5];
    const float* score = (const float*)d_in[6];
    float* out = (float*)d_out;

    zero_kernel<<<(B_ * (GG_ + 1) + 255) / 256, 256>>>();

    const int prep_threads = (N_ * 64) / 4 + N_ + NE_ / 4 + 3 * (N_ / 4);
    prep_kernel<<<(prep_threads + 255) / 256, 256>>>(x, pos, perm, score, out);

    scan_kernel<<<B_, 1024>>>();
    scatter_kernel<<<N_ / 128, 128>>>(out);
    knn_kernel<<<N_ / 128, 128>>>(out);
    norm_kernel<<<(NE_ / 4) / 256, 256>>>(out);
}